// round 1
// baseline (speedup 1.0000x reference)
#include <cuda_runtime.h>
#include <cuda_bf16.h>
#include <math.h>

#define HDIM 1024
#define BDIM 128
#define TDIM 128
#define G3   (3 * HDIM)

// ----------------------------- scratch (device globals; no allocation) ------
__device__ float g_gates_p[(size_t)BDIM * TDIM * G3];   // [B,T,3H]
__device__ float g_gates_h[(size_t)BDIM * TDIM * G3];   // [B,T,3H]
__device__ float g_op[(size_t)TDIM * BDIM * HDIM];      // premise outputs == h states, [T,B,H]
__device__ float g_hbuf[2 * BDIM * HDIM];               // hypothesis h ping-pong
__device__ float g_WyM[(size_t)TDIM * BDIM * HDIM];     // Wy, [T,B,H] row order
__device__ float g_Wh[BDIM * HDIM];
__device__ float g_r[BDIM * HDIM];
__device__ float g_G1[BDIM * HDIM];
__device__ float g_G2[BDIM * HDIM];
__device__ float g_hstar[BDIM * HDIM];

__device__ __forceinline__ float sigmoidf_(float x) { return 1.0f / (1.0f + expf(-x)); }

// ----------------------------- generic fp32 GEMM, 128x128 tile, Kt=8 --------
// C[M,N] = A[M,K] * op(B) (+ bias[n]).  TRANSB: B is [N,K] row-major (weights
// like W_ih[g,h]); else B is [K,N] row-major.
// Requires M%128==0, N%128==0, K%8==0, 256 threads.
template <bool TRANSB, bool BIAS>
__global__ void gemm_tiled(const float* __restrict__ A, const float* __restrict__ Bm,
                           const float* __restrict__ bias, float* __restrict__ C,
                           int M, int N, int K)
{
    __shared__ float As[8][132];
    __shared__ float Bs[8][132];

    const int tid = threadIdx.x;
    const int tx = tid & 15, ty = tid >> 4;
    const int m0 = blockIdx.y * 128, n0 = blockIdx.x * 128;

    float acc[8][8];
#pragma unroll
    for (int i = 0; i < 8; i++)
#pragma unroll
        for (int j = 0; j < 8; j++) acc[i][j] = 0.f;

    const int a_row = tid >> 1;
    const int a_k4  = (tid & 1) * 4;
    const int b_kr  = tid >> 5;          // normal-B
    const int b_n4  = (tid & 31) * 4;

    for (int k0 = 0; k0 < K; k0 += 8) {
        float4 av = *(const float4*)&A[(size_t)(m0 + a_row) * K + k0 + a_k4];
        As[a_k4 + 0][a_row] = av.x;
        As[a_k4 + 1][a_row] = av.y;
        As[a_k4 + 2][a_row] = av.z;
        As[a_k4 + 3][a_row] = av.w;
        if (TRANSB) {
            float4 bv = *(const float4*)&Bm[(size_t)(n0 + a_row) * K + k0 + a_k4];
            Bs[a_k4 + 0][a_row] = bv.x;
            Bs[a_k4 + 1][a_row] = bv.y;
            Bs[a_k4 + 2][a_row] = bv.z;
            Bs[a_k4 + 3][a_row] = bv.w;
        } else {
            float4 bv = *(const float4*)&Bm[(size_t)(k0 + b_kr) * N + n0 + b_n4];
            Bs[b_kr][b_n4 + 0] = bv.x;
            Bs[b_kr][b_n4 + 1] = bv.y;
            Bs[b_kr][b_n4 + 2] = bv.z;
            Bs[b_kr][b_n4 + 3] = bv.w;
        }
        __syncthreads();
#pragma unroll
        for (int kk = 0; kk < 8; kk++) {
            float a[8], b[8];
#pragma unroll
            for (int i = 0; i < 8; i++) a[i] = As[kk][ty + 16 * i];
#pragma unroll
            for (int j = 0; j < 8; j++) b[j] = Bs[kk][tx + 16 * j];
#pragma unroll
            for (int i = 0; i < 8; i++)
#pragma unroll
                for (int j = 0; j < 8; j++) acc[i][j] += a[i] * b[j];
        }
        __syncthreads();
    }

#pragma unroll
    for (int i = 0; i < 8; i++) {
        int m = m0 + ty + 16 * i;
#pragma unroll
        for (int j = 0; j < 8; j++) {
            int n = n0 + tx + 16 * j;
            float v = acc[i][j];
            if (BIAS) v += bias[n];
            C[(size_t)m * N + n] = v;
        }
    }
}

// ----------------------------- fused GRU step --------------------------------
// h_out[b,c] from h_in (nullptr -> zeros), gates gx[B,T,3H] at timestep t,
// W_hh[3H,H], b_hh[3H].  grid=128 (8 cols each), 256 threads:
// thread handles 4 batch rows x 1 col x 3 gates.
__global__ void gru_step(const float* __restrict__ h_in, float* __restrict__ h_out,
                         const float* __restrict__ gx, const float* __restrict__ Whh,
                         const float* __restrict__ bhh, int t)
{
    __shared__ float Hs[128][33];
    __shared__ float Ws[24][33];

    const int tid = threadIdx.x;
    const int j  = tid & 7;
    const int b0 = (tid >> 3) * 4;
    const int hc = blockIdx.x * 8;

    float aR[4] = {0.f, 0.f, 0.f, 0.f};
    float aZ[4] = {0.f, 0.f, 0.f, 0.f};
    float aN[4] = {0.f, 0.f, 0.f, 0.f};

    if (h_in) {
        for (int k0 = 0; k0 < HDIM; k0 += 32) {
            // load H tile [128 x 32]
#pragma unroll
            for (int r = 0; r < 4; r++) {
                int f  = tid + r * 256;        // 0..1023
                int b  = f >> 3;
                int kq = (f & 7) * 4;
                float4 hv = *(const float4*)&h_in[(size_t)b * HDIM + k0 + kq];
                Hs[b][kq + 0] = hv.x;
                Hs[b][kq + 1] = hv.y;
                Hs[b][kq + 2] = hv.z;
                Hs[b][kq + 3] = hv.w;
            }
            // load W tile [24 x 32]: rows {hc..hc+7, H+hc.., 2H+hc..}
#pragma unroll
            for (int w = 0; w < 3; w++) {
                int idx = w * 256 + tid;       // 0..767
                int gl  = idx >> 5;            // 0..23
                int kk  = idx & 31;
                int row = (gl >> 3) * HDIM + hc + (gl & 7);
                Ws[gl][kk] = Whh[(size_t)row * HDIM + k0 + kk];
            }
            __syncthreads();
#pragma unroll
            for (int kk = 0; kk < 32; kk++) {
                float w0 = Ws[j][kk], w1 = Ws[8 + j][kk], w2 = Ws[16 + j][kk];
#pragma unroll
                for (int i = 0; i < 4; i++) {
                    float hv = Hs[b0 + i][kk];
                    aR[i] += hv * w0;
                    aZ[i] += hv * w1;
                    aN[i] += hv * w2;
                }
            }
            __syncthreads();
        }
    }

    const int col = hc + j;
    const float br = bhh[col], bz = bhh[HDIM + col], bn = bhh[2 * HDIM + col];
#pragma unroll
    for (int i = 0; i < 4; i++) {
        int b = b0 + i;
        const float* gxp = gx + ((size_t)b * TDIM + t) * G3;
        float r = sigmoidf_(gxp[col] + aR[i] + br);
        float z = sigmoidf_(gxp[HDIM + col] + aZ[i] + bz);
        float n = tanhf(gxp[2 * HDIM + col] + r * (aN[i] + bn));
        float hp = h_in ? h_in[(size_t)b * HDIM + col] : 0.f;
        h_out[(size_t)b * HDIM + col] = (1.f - z) * n + z * hp;
    }
}

// ----------------------------- attention: scores -> softmax -> context ------
// One block per batch row b. WyM[T,B,H] (row t*B+b), Wh[B,H], Walpha[H],
// op[T,B,H] -> rout[B,H].
__global__ void attn_kernel(const float* __restrict__ WyM, const float* __restrict__ Wh,
                            const float* __restrict__ Walpha, const float* __restrict__ op,
                            float* __restrict__ rout)
{
    __shared__ float sc[128];
    __shared__ float red[256];
    const int b = blockIdx.x;
    const int tid = threadIdx.x;
    const int lane = tid & 31;
    const int warp = tid >> 5;

    // scores[t] = sum_d tanh(WyM[t,b,d] + Wh[b,d]) * Walpha[d]
    for (int t = warp; t < TDIM; t += 8) {
        const float* wy = WyM + ((size_t)t * BDIM + b) * HDIM;
        const float* wh = Wh + (size_t)b * HDIM;
        float s = 0.f;
        for (int d = lane; d < HDIM; d += 32)
            s += tanhf(wy[d] + wh[d]) * Walpha[d];
#pragma unroll
        for (int o = 16; o > 0; o >>= 1) s += __shfl_xor_sync(0xffffffffu, s, o);
        if (lane == 0) sc[t] = s;
    }
    __syncthreads();

    // softmax over 128
    float v = (tid < 128) ? sc[tid] : -INFINITY;
    red[tid] = v;
    __syncthreads();
    for (int s = 128; s > 0; s >>= 1) {
        if (tid < s) red[tid] = fmaxf(red[tid], red[tid + s]);
        __syncthreads();
    }
    float mx = red[0];
    __syncthreads();
    float e = (tid < 128) ? expf(sc[tid] - mx) : 0.f;
    red[tid] = e;
    __syncthreads();
    for (int s = 128; s > 0; s >>= 1) {
        if (tid < s) red[tid] += red[tid + s];
        __syncthreads();
    }
    float sum = red[0];
    __syncthreads();
    if (tid < 128) sc[tid] = e / sum;
    __syncthreads();

    // context r[b,h] = sum_t alpha[t] * op[t,b,h]
    for (int h = tid; h < HDIM; h += 256) {
        float acc = 0.f;
        for (int t = 0; t < TDIM; t++)
            acc += sc[t] * op[((size_t)t * BDIM + b) * HDIM + h];
        rout[(size_t)b * HDIM + h] = acc;
    }
}

__global__ void combine_tanh(const float* __restrict__ a, const float* __restrict__ b,
                             float* __restrict__ c, int n)
{
    int i = blockIdx.x * blockDim.x + threadIdx.x;
    if (i < n) c[i] = tanhf(a[i] + b[i]);
}

// logits = tanh(hstar @ out_w^T + out_b); out = log_softmax(logits)
__global__ void final_kernel(const float* __restrict__ hstar, const float* __restrict__ outw,
                             const float* __restrict__ outb, float* __restrict__ out)
{
    __shared__ float red[128];
    __shared__ float lg[3];
    const int b = blockIdx.x;
    const int tid = threadIdx.x;

    for (int c = 0; c < 3; c++) {
        float p = 0.f;
        for (int h = tid; h < HDIM; h += 128)
            p += hstar[(size_t)b * HDIM + h] * outw[(size_t)c * HDIM + h];
        red[tid] = p;
        __syncthreads();
        for (int s = 64; s > 0; s >>= 1) {
            if (tid < s) red[tid] += red[tid + s];
            __syncthreads();
        }
        if (tid == 0) lg[c] = tanhf(red[0] + outb[c]);
        __syncthreads();
    }
    if (tid == 0) {
        float m = fmaxf(lg[0], fmaxf(lg[1], lg[2]));
        float s = expf(lg[0] - m) + expf(lg[1] - m) + expf(lg[2] - m);
        float lse = logf(s);
        for (int c = 0; c < 3; c++) out[b * 3 + c] = lg[c] - m - lse;
    }
}

// ----------------------------- launch ----------------------------------------
extern "C" void kernel_launch(void* const* d_in, const int* in_sizes, int n_in,
                              void* d_out, int out_size)
{
    const float* premise    = (const float*)d_in[0];
    const float* hypothesis = (const float*)d_in[1];
    const float* p_Wih = (const float*)d_in[2];
    const float* p_Whh = (const float*)d_in[3];
    const float* p_bih = (const float*)d_in[4];
    const float* p_bhh = (const float*)d_in[5];
    const float* h_Wih = (const float*)d_in[6];
    const float* h_Whh = (const float*)d_in[7];
    const float* h_bih = (const float*)d_in[8];
    const float* h_bhh = (const float*)d_in[9];
    const float* W_y     = (const float*)d_in[10];
    const float* W_h     = (const float*)d_in[11];
    const float* W_alpha = (const float*)d_in[12];
    const float* W_x     = (const float*)d_in[13];
    const float* W_p     = (const float*)d_in[14];
    const float* out_w   = (const float*)d_in[15];
    const float* out_b   = (const float*)d_in[16];

    float *gates_p, *gates_h, *op, *hbuf, *WyM, *Whs, *rs, *G1, *G2, *hstar;
    cudaGetSymbolAddress((void**)&gates_p, g_gates_p);
    cudaGetSymbolAddress((void**)&gates_h, g_gates_h);
    cudaGetSymbolAddress((void**)&op,      g_op);
    cudaGetSymbolAddress((void**)&hbuf,    g_hbuf);
    cudaGetSymbolAddress((void**)&WyM,     g_WyM);
    cudaGetSymbolAddress((void**)&Whs,     g_Wh);
    cudaGetSymbolAddress((void**)&rs,      g_r);
    cudaGetSymbolAddress((void**)&G1,      g_G1);
    cudaGetSymbolAddress((void**)&G2,      g_G2);
    cudaGetSymbolAddress((void**)&hstar,   g_hstar);

    const int MB = TDIM * BDIM;   // 16384 rows

    // input-gate GEMMs: gates[b,t,g] = premise[b,t,:] . W_ih[g,:] + b_ih[g]
    gemm_tiled<true, true><<<dim3(G3 / 128, MB / 128), 256>>>(
        premise, p_Wih, p_bih, gates_p, MB, G3, HDIM);
    gemm_tiled<true, true><<<dim3(G3 / 128, MB / 128), 256>>>(
        hypothesis, h_Wih, h_bih, gates_h, MB, G3, HDIM);

    // premise scan: h states live in g_op rows
    for (int t = 0; t < TDIM; t++) {
        const float* hin = t ? op + (size_t)(t - 1) * BDIM * HDIM : nullptr;
        gru_step<<<128, 256>>>(hin, op + (size_t)t * BDIM * HDIM,
                               gates_p, p_Whh, p_bhh, t);
    }
    // hypothesis scan: starts from premise final state; ping-pong
    for (int t = 0; t < TDIM; t++) {
        const float* hin = (t == 0) ? op + (size_t)(TDIM - 1) * BDIM * HDIM
                                    : hbuf + (size_t)((t - 1) & 1) * BDIM * HDIM;
        gru_step<<<128, 256>>>(hin, hbuf + (size_t)(t & 1) * BDIM * HDIM,
                               gates_h, h_Whh, h_bhh, t);
    }
    const float* hlast = hbuf + (size_t)((TDIM - 1) & 1) * BDIM * HDIM;

    // attention
    gemm_tiled<false, false><<<dim3(HDIM / 128, MB / 128), 256>>>(
        op, W_y, nullptr, WyM, MB, HDIM, HDIM);
    gemm_tiled<false, false><<<dim3(HDIM / 128, 1), 256>>>(
        hlast, W_h, nullptr, Whs, BDIM, HDIM, HDIM);
    attn_kernel<<<128, 256>>>(WyM, Whs, W_alpha, op, rs);

    // h_star and classifier
    gemm_tiled<false, false><<<dim3(HDIM / 128, 1), 256>>>(
        rs, W_p, nullptr, G1, BDIM, HDIM, HDIM);
    gemm_tiled<false, false><<<dim3(HDIM / 128, 1), 256>>>(
        hlast, W_x, nullptr, G2, BDIM, HDIM, HDIM);
    combine_tanh<<<(BDIM * HDIM + 255) / 256, 256>>>(G1, G2, hstar, BDIM * HDIM);
    final_kernel<<<128, 128>>>(hstar, out_w, out_b, (float*)d_out);
}

// round 2
// speedup vs baseline: 1.5849x; 1.5849x over previous
#include <cuda_runtime.h>
#include <cuda_bf16.h>
#include <math.h>
#include <stdint.h>

#define HDIM 1024
#define BDIM 128
#define TDIM 128
#define G3   (3 * HDIM)
#define BH   (BDIM * HDIM)

// ----------------------------- scratch (device globals; no allocation) ------
__device__ float g_gates_p[(size_t)BDIM * TDIM * G3];   // [B,T,3H]
__device__ float g_gates_h[(size_t)BDIM * TDIM * G3];   // [B,T,3H]
__device__ float g_op[(size_t)TDIM * BDIM * HDIM];      // premise h states, [T,B,H]
__device__ float g_hbuf[2 * BH];                        // hypothesis h ping-pong (fp32)
__device__ __nv_bfloat16 g_hhi[2 * BH];                 // h bf16 hi ping-pong
__device__ __nv_bfloat16 g_hlo[2 * BH];                 // h bf16 lo ping-pong
__device__ __nv_bfloat16 g_whi_p[(size_t)G3 * HDIM];
__device__ __nv_bfloat16 g_wlo_p[(size_t)G3 * HDIM];
__device__ __nv_bfloat16 g_whi_h[(size_t)G3 * HDIM];
__device__ __nv_bfloat16 g_wlo_h[(size_t)G3 * HDIM];
__device__ float g_WyT[HDIM * HDIM];                    // W_y transposed -> [N,K]
__device__ float g_WyM[(size_t)TDIM * BDIM * HDIM];     // Wy, [T,B,H]
__device__ float g_Wh[BH];
__device__ float g_r[BH];
__device__ float g_G1[BH];
__device__ float g_G2[BH];
__device__ float g_hstar[BH];

__device__ __forceinline__ float sigmoidf_(float x) { return 1.0f / (1.0f + expf(-x)); }

__device__ __forceinline__ uint32_t f2tf32(float x) {
    uint32_t r;
    asm("cvt.rna.tf32.f32 %0, %1;" : "=r"(r) : "f"(x));
    return r;
}

__device__ __forceinline__ void mma_tf32(float* d, const uint32_t* a, const uint32_t* b) {
    asm("mma.sync.aligned.m16n8k8.row.col.f32.tf32.tf32.f32 "
        "{%0,%1,%2,%3},{%4,%5,%6,%7},{%8,%9},{%0,%1,%2,%3};"
        : "+f"(d[0]), "+f"(d[1]), "+f"(d[2]), "+f"(d[3])
        : "r"(a[0]), "r"(a[1]), "r"(a[2]), "r"(a[3]), "r"(b[0]), "r"(b[1]));
}

__device__ __forceinline__ void mma_bf16(float* d, const uint32_t* a, const uint32_t* b) {
    asm("mma.sync.aligned.m16n8k16.row.col.f32.bf16.bf16.f32 "
        "{%0,%1,%2,%3},{%4,%5,%6,%7},{%8,%9},{%0,%1,%2,%3};"
        : "+f"(d[0]), "+f"(d[1]), "+f"(d[2]), "+f"(d[3])
        : "r"(a[0]), "r"(a[1]), "r"(a[2]), "r"(a[3]), "r"(b[0]), "r"(b[1]));
}

// ----------------------------- weight split fp32 -> bf16 hi/lo ---------------
__global__ void split_w(const float* __restrict__ W, __nv_bfloat16* __restrict__ hi,
                        __nv_bfloat16* __restrict__ lo, int n)
{
    int i = blockIdx.x * blockDim.x + threadIdx.x;
    if (i < n) {
        float v = W[i];
        __nv_bfloat16 h = __float2bfloat16(v);
        hi[i] = h;
        lo[i] = __float2bfloat16(v - __bfloat162float(h));
    }
}

// ----------------------------- 1024x1024 transpose ---------------------------
__global__ void transpose1024(const float* __restrict__ in, float* __restrict__ out)
{
    __shared__ float t[32][33];
    int x = blockIdx.x * 32 + threadIdx.x;
    int y0 = blockIdx.y * 32;
    for (int r = threadIdx.y; r < 32; r += 8)
        t[r][threadIdx.x] = in[(size_t)(y0 + r) * HDIM + x];
    __syncthreads();
    int xo = blockIdx.y * 32 + threadIdx.x;
    for (int r = threadIdx.y; r < 32; r += 8)
        out[(size_t)(blockIdx.x * 32 + r) * HDIM + xo] = t[threadIdx.x][r];
}

// ----------------------------- tf32 mma GEMM: C[M,N] = A[M,K]*B[N,K]^T (+bias)
// block 128x128, 256 thr (8 warps: 4 in m x 2 in n), warp tile 32x64, Kc=32.
template <bool BIAS>
__global__ void __launch_bounds__(256) gemm_tf32(
    const float* __restrict__ A, const float* __restrict__ Bw,
    const float* __restrict__ bias, float* __restrict__ C,
    int M, int N, int K)
{
    __shared__ uint32_t As[32][132];
    __shared__ uint32_t Bs[32][132];

    const int tid = threadIdx.x;
    const int lane = tid & 31, wid = tid >> 5;
    const int g = lane >> 2, tg = lane & 3;
    const int wm = (wid & 3) * 32;
    const int wn = (wid >> 2) * 64;
    const int m0 = blockIdx.y * 128, n0 = blockIdx.x * 128;

    float acc[2][8][4];
#pragma unroll
    for (int a = 0; a < 2; a++)
#pragma unroll
        for (int b = 0; b < 8; b++)
#pragma unroll
            for (int c = 0; c < 4; c++) acc[a][b][c] = 0.f;

    for (int k0 = 0; k0 < K; k0 += 32) {
#pragma unroll
        for (int r = 0; r < 4; r++) {
            int idx = tid + r * 256;
            int row = idx >> 3, kq = (idx & 7) * 4;
            float4 av = *(const float4*)&A[(size_t)(m0 + row) * K + k0 + kq];
            As[kq + 0][row] = f2tf32(av.x);
            As[kq + 1][row] = f2tf32(av.y);
            As[kq + 2][row] = f2tf32(av.z);
            As[kq + 3][row] = f2tf32(av.w);
            float4 bv = *(const float4*)&Bw[(size_t)(n0 + row) * K + k0 + kq];
            Bs[kq + 0][row] = f2tf32(bv.x);
            Bs[kq + 1][row] = f2tf32(bv.y);
            Bs[kq + 2][row] = f2tf32(bv.z);
            Bs[kq + 3][row] = f2tf32(bv.w);
        }
        __syncthreads();
#pragma unroll
        for (int kk = 0; kk < 32; kk += 8) {
            uint32_t af[2][4], bf[8][2];
#pragma unroll
            for (int mt = 0; mt < 2; mt++) {
                af[mt][0] = As[kk + tg][wm + mt * 16 + g];
                af[mt][1] = As[kk + tg][wm + mt * 16 + g + 8];
                af[mt][2] = As[kk + tg + 4][wm + mt * 16 + g];
                af[mt][3] = As[kk + tg + 4][wm + mt * 16 + g + 8];
            }
#pragma unroll
            for (int nt = 0; nt < 8; nt++) {
                bf[nt][0] = Bs[kk + tg][wn + nt * 8 + g];
                bf[nt][1] = Bs[kk + tg + 4][wn + nt * 8 + g];
            }
#pragma unroll
            for (int mt = 0; mt < 2; mt++)
#pragma unroll
                for (int nt = 0; nt < 8; nt++)
                    mma_tf32(acc[mt][nt], af[mt], bf[nt]);
        }
        __syncthreads();
    }

#pragma unroll
    for (int mt = 0; mt < 2; mt++) {
#pragma unroll
        for (int nt = 0; nt < 8; nt++) {
            int row = m0 + wm + mt * 16 + g;
            int col = n0 + wn + nt * 8 + 2 * tg;
            float b0 = BIAS ? bias[col] : 0.f;
            float b1 = BIAS ? bias[col + 1] : 0.f;
            C[(size_t)row * N + col]       = acc[mt][nt][0] + b0;
            C[(size_t)row * N + col + 1]   = acc[mt][nt][1] + b1;
            C[(size_t)(row + 8) * N + col]     = acc[mt][nt][2] + b0;
            C[(size_t)(row + 8) * N + col + 1] = acc[mt][nt][3] + b1;
        }
    }
}

// ----------------------------- GRU step via bf16 split mma -------------------
// grid=128 blocks: block owns 8 h-cols (24 gate rows). 8 warps: warp w = batch
// rows 16w..16w+15. K chunk 64 (4 x k16).
__global__ void __launch_bounds__(256) gru_step_mma(
    const float* __restrict__ hprev,            // [128,1024] fp32 or null
    const __nv_bfloat16* __restrict__ ahi,      // [128,1024]
    const __nv_bfloat16* __restrict__ alo,
    float* __restrict__ hout,
    __nv_bfloat16* __restrict__ ohi,
    __nv_bfloat16* __restrict__ olo,
    const float* __restrict__ gx,               // [B,T,3H]
    const __nv_bfloat16* __restrict__ Whi,      // [3072,1024]
    const __nv_bfloat16* __restrict__ Wlo,
    const float* __restrict__ bhh, int t)
{
    __shared__ uint32_t Ah[128][36];
    __shared__ uint32_t Al[128][36];
    __shared__ uint32_t Bh[24][36];
    __shared__ uint32_t Bl[24][36];

    const int tid = threadIdx.x, lane = tid & 31, wid = tid >> 5;
    const int g = lane >> 2, tg = lane & 3;
    const int hc = blockIdx.x * 8;

    float acc[3][4];
#pragma unroll
    for (int a = 0; a < 3; a++)
#pragma unroll
        for (int c = 0; c < 4; c++) acc[a][c] = 0.f;

    if (hprev) {
        for (int k0 = 0; k0 < HDIM; k0 += 64) {
#pragma unroll
            for (int r = 0; r < 4; r++) {
                int idx = tid + r * 256;
                int row = idx >> 3, c = idx & 7;
                uint4 v = *(const uint4*)&ahi[(size_t)row * HDIM + k0 + c * 8];
                *(uint4*)&Ah[row][c * 4] = v;
                uint4 w = *(const uint4*)&alo[(size_t)row * HDIM + k0 + c * 8];
                *(uint4*)&Al[row][c * 4] = w;
            }
            if (tid < 192) {
                int row = tid >> 3, c = tid & 7;
                int gr = (row >> 3) * HDIM + hc + (row & 7);
                uint4 v = *(const uint4*)&Whi[(size_t)gr * HDIM + k0 + c * 8];
                *(uint4*)&Bh[row][c * 4] = v;
                uint4 w = *(const uint4*)&Wlo[(size_t)gr * HDIM + k0 + c * 8];
                *(uint4*)&Bl[row][c * 4] = w;
            }
            __syncthreads();
#pragma unroll
            for (int s = 0; s < 4; s++) {
                int kc = s * 8;
                uint32_t AH[4], AL[4];
                AH[0] = Ah[wid * 16 + g][kc + tg];
                AH[1] = Ah[wid * 16 + g + 8][kc + tg];
                AH[2] = Ah[wid * 16 + g][kc + tg + 4];
                AH[3] = Ah[wid * 16 + g + 8][kc + tg + 4];
                AL[0] = Al[wid * 16 + g][kc + tg];
                AL[1] = Al[wid * 16 + g + 8][kc + tg];
                AL[2] = Al[wid * 16 + g][kc + tg + 4];
                AL[3] = Al[wid * 16 + g + 8][kc + tg + 4];
#pragma unroll
                for (int gt = 0; gt < 3; gt++) {
                    uint32_t BH_[2], BL_[2];
                    BH_[0] = Bh[gt * 8 + g][kc + tg];
                    BH_[1] = Bh[gt * 8 + g][kc + tg + 4];
                    BL_[0] = Bl[gt * 8 + g][kc + tg];
                    BL_[1] = Bl[gt * 8 + g][kc + tg + 4];
                    mma_bf16(acc[gt], AH, BH_);
                    mma_bf16(acc[gt], AH, BL_);
                    mma_bf16(acc[gt], AL, BH_);
                }
            }
            __syncthreads();
        }
    }

    // epilogue: thread owns batches {16w+g, 16w+g+8} x cols {hc+2tg, hc+2tg+1}
    const int brow = wid * 16 + g;
#pragma unroll
    for (int i = 0; i < 2; i++) {
        int b = brow + i * 8;
#pragma unroll
        for (int jj = 0; jj < 2; jj++) {
            int col = hc + 2 * tg + jj;
            int ai = i * 2 + jj;
            size_t gbase = ((size_t)b * TDIM + t) * G3;
            float r = sigmoidf_(gx[gbase + col] + acc[0][ai] + bhh[col]);
            float z = sigmoidf_(gx[gbase + HDIM + col] + acc[1][ai] + bhh[HDIM + col]);
            float n = tanhf(gx[gbase + 2 * HDIM + col] + r * (acc[2][ai] + bhh[2 * HDIM + col]));
            float hp = hprev ? hprev[(size_t)b * HDIM + col] : 0.f;
            float h = (1.f - z) * n + z * hp;
            size_t oi = (size_t)b * HDIM + col;
            hout[oi] = h;
            __nv_bfloat16 hb = __float2bfloat16(h);
            ohi[oi] = hb;
            olo[oi] = __float2bfloat16(h - __bfloat162float(hb));
        }
    }
}

// ----------------------------- fp32 GEMM for small matmuls -------------------
template <bool TRANSB, bool BIAS>
__global__ void gemm_tiled(const float* __restrict__ A, const float* __restrict__ Bm,
                           const float* __restrict__ bias, float* __restrict__ C,
                           int M, int N, int K)
{
    __shared__ float As[8][132];
    __shared__ float Bs[8][132];

    const int tid = threadIdx.x;
    const int tx = tid & 15, ty = tid >> 4;
    const int m0 = blockIdx.y * 128, n0 = blockIdx.x * 128;

    float acc[8][8];
#pragma unroll
    for (int i = 0; i < 8; i++)
#pragma unroll
        for (int j = 0; j < 8; j++) acc[i][j] = 0.f;

    const int a_row = tid >> 1;
    const int a_k4  = (tid & 1) * 4;
    const int b_kr  = tid >> 5;
    const int b_n4  = (tid & 31) * 4;

    for (int k0 = 0; k0 < K; k0 += 8) {
        float4 av = *(const float4*)&A[(size_t)(m0 + a_row) * K + k0 + a_k4];
        As[a_k4 + 0][a_row] = av.x;
        As[a_k4 + 1][a_row] = av.y;
        As[a_k4 + 2][a_row] = av.z;
        As[a_k4 + 3][a_row] = av.w;
        if (TRANSB) {
            float4 bv = *(const float4*)&Bm[(size_t)(n0 + a_row) * K + k0 + a_k4];
            Bs[a_k4 + 0][a_row] = bv.x;
            Bs[a_k4 + 1][a_row] = bv.y;
            Bs[a_k4 + 2][a_row] = bv.z;
            Bs[a_k4 + 3][a_row] = bv.w;
        } else {
            float4 bv = *(const float4*)&Bm[(size_t)(k0 + b_kr) * N + n0 + b_n4];
            Bs[b_kr][b_n4 + 0] = bv.x;
            Bs[b_kr][b_n4 + 1] = bv.y;
            Bs[b_kr][b_n4 + 2] = bv.z;
            Bs[b_kr][b_n4 + 3] = bv.w;
        }
        __syncthreads();
#pragma unroll
        for (int kk = 0; kk < 8; kk++) {
            float a[8], b[8];
#pragma unroll
            for (int i = 0; i < 8; i++) a[i] = As[kk][ty + 16 * i];
#pragma unroll
            for (int j = 0; j < 8; j++) b[j] = Bs[kk][tx + 16 * j];
#pragma unroll
            for (int i = 0; i < 8; i++)
#pragma unroll
                for (int j = 0; j < 8; j++) acc[i][j] += a[i] * b[j];
        }
        __syncthreads();
    }

#pragma unroll
    for (int i = 0; i < 8; i++) {
        int m = m0 + ty + 16 * i;
#pragma unroll
        for (int j = 0; j < 8; j++) {
            int n = n0 + tx + 16 * j;
            float v = acc[i][j];
            if (BIAS) v += bias[n];
            C[(size_t)m * N + n] = v;
        }
    }
}

// ----------------------------- attention -------------------------------------
__global__ void attn_kernel(const float* __restrict__ WyM, const float* __restrict__ Wh,
                            const float* __restrict__ Walpha, const float* __restrict__ op,
                            float* __restrict__ rout)
{
    __shared__ float sc[128];
    __shared__ float red[256];
    const int b = blockIdx.x;
    const int tid = threadIdx.x;
    const int lane = tid & 31;
    const int warp = tid >> 5;

    for (int t = warp; t < TDIM; t += 8) {
        const float* wy = WyM + ((size_t)t * BDIM + b) * HDIM;
        const float* wh = Wh + (size_t)b * HDIM;
        float s = 0.f;
        for (int d = lane; d < HDIM; d += 32)
            s += tanhf(wy[d] + wh[d]) * Walpha[d];
#pragma unroll
        for (int o = 16; o > 0; o >>= 1) s += __shfl_xor_sync(0xffffffffu, s, o);
        if (lane == 0) sc[t] = s;
    }
    __syncthreads();

    float v = (tid < 128) ? sc[tid] : -INFINITY;
    red[tid] = v;
    __syncthreads();
    for (int s = 128; s > 0; s >>= 1) {
        if (tid < s) red[tid] = fmaxf(red[tid], red[tid + s]);
        __syncthreads();
    }
    float mx = red[0];
    __syncthreads();
    float e = (tid < 128) ? expf(sc[tid] - mx) : 0.f;
    red[tid] = e;
    __syncthreads();
    for (int s = 128; s > 0; s >>= 1) {
        if (tid < s) red[tid] += red[tid + s];
        __syncthreads();
    }
    float sum = red[0];
    __syncthreads();
    if (tid < 128) sc[tid] = e / sum;
    __syncthreads();

    for (int h = tid; h < HDIM; h += 256) {
        float acc = 0.f;
        for (int t = 0; t < TDIM; t++)
            acc += sc[t] * op[((size_t)t * BDIM + b) * HDIM + h];
        rout[(size_t)b * HDIM + h] = acc;
    }
}

__global__ void combine_tanh(const float* __restrict__ a, const float* __restrict__ b,
                             float* __restrict__ c, int n)
{
    int i = blockIdx.x * blockDim.x + threadIdx.x;
    if (i < n) c[i] = tanhf(a[i] + b[i]);
}

__global__ void final_kernel(const float* __restrict__ hstar, const float* __restrict__ outw,
                             const float* __restrict__ outb, float* __restrict__ out)
{
    __shared__ float red[128];
    __shared__ float lg[3];
    const int b = blockIdx.x;
    const int tid = threadIdx.x;

    for (int c = 0; c < 3; c++) {
        float p = 0.f;
        for (int h = tid; h < HDIM; h += 128)
            p += hstar[(size_t)b * HDIM + h] * outw[(size_t)c * HDIM + h];
        red[tid] = p;
        __syncthreads();
        for (int s = 64; s > 0; s >>= 1) {
            if (tid < s) red[tid] += red[tid + s];
            __syncthreads();
        }
        if (tid == 0) lg[c] = tanhf(red[0] + outb[c]);
        __syncthreads();
    }
    if (tid == 0) {
        float m = fmaxf(lg[0], fmaxf(lg[1], lg[2]));
        float s = expf(lg[0] - m) + expf(lg[1] - m) + expf(lg[2] - m);
        float lse = logf(s);
        for (int c = 0; c < 3; c++) out[b * 3 + c] = lg[c] - m - lse;
    }
}

// ----------------------------- launch ----------------------------------------
extern "C" void kernel_launch(void* const* d_in, const int* in_sizes, int n_in,
                              void* d_out, int out_size)
{
    const float* premise    = (const float*)d_in[0];
    const float* hypothesis = (const float*)d_in[1];
    const float* p_Wih = (const float*)d_in[2];
    const float* p_Whh = (const float*)d_in[3];
    const float* p_bih = (const float*)d_in[4];
    const float* p_bhh = (const float*)d_in[5];
    const float* h_Wih = (const float*)d_in[6];
    const float* h_Whh = (const float*)d_in[7];
    const float* h_bih = (const float*)d_in[8];
    const float* h_bhh = (const float*)d_in[9];
    const float* W_y     = (const float*)d_in[10];
    const float* W_h     = (const float*)d_in[11];
    const float* W_alpha = (const float*)d_in[12];
    const float* W_x     = (const float*)d_in[13];
    const float* W_p     = (const float*)d_in[14];
    const float* out_w   = (const float*)d_in[15];
    const float* out_b   = (const float*)d_in[16];

    float *gates_p, *gates_h, *op, *hbuf, *WyT, *WyM, *Whs, *rs, *G1, *G2, *hstar;
    __nv_bfloat16 *hhi, *hlo, *whi_p, *wlo_p, *whi_h, *wlo_h;
    cudaGetSymbolAddress((void**)&gates_p, g_gates_p);
    cudaGetSymbolAddress((void**)&gates_h, g_gates_h);
    cudaGetSymbolAddress((void**)&op,      g_op);
    cudaGetSymbolAddress((void**)&hbuf,    g_hbuf);
    cudaGetSymbolAddress((void**)&hhi,     g_hhi);
    cudaGetSymbolAddress((void**)&hlo,     g_hlo);
    cudaGetSymbolAddress((void**)&whi_p,   g_whi_p);
    cudaGetSymbolAddress((void**)&wlo_p,   g_wlo_p);
    cudaGetSymbolAddress((void**)&whi_h,   g_whi_h);
    cudaGetSymbolAddress((void**)&wlo_h,   g_wlo_h);
    cudaGetSymbolAddress((void**)&WyT,     g_WyT);
    cudaGetSymbolAddress((void**)&WyM,     g_WyM);
    cudaGetSymbolAddress((void**)&Whs,     g_Wh);
    cudaGetSymbolAddress((void**)&rs,      g_r);
    cudaGetSymbolAddress((void**)&G1,      g_G1);
    cudaGetSymbolAddress((void**)&G2,      g_G2);
    cudaGetSymbolAddress((void**)&hstar,   g_hstar);

    const int MB = TDIM * BDIM;   // 16384

    // prep: weight splits + W_y transpose
    split_w<<<(G3 * HDIM + 255) / 256, 256>>>(p_Whh, whi_p, wlo_p, G3 * HDIM);
    split_w<<<(G3 * HDIM + 255) / 256, 256>>>(h_Whh, whi_h, wlo_h, G3 * HDIM);
    transpose1024<<<dim3(32, 32), dim3(32, 8)>>>(W_y, WyT);

    // input-gate GEMMs (tf32 tensor cores)
    gemm_tf32<true><<<dim3(G3 / 128, MB / 128), 256>>>(
        premise, p_Wih, p_bih, gates_p, MB, G3, HDIM);
    gemm_tf32<true><<<dim3(G3 / 128, MB / 128), 256>>>(
        hypothesis, h_Wih, h_bih, gates_h, MB, G3, HDIM);

    // premise scan (h fp32 rows live in g_op; bf16 hi/lo ping-pong)
    for (int t = 0; t < TDIM; t++) {
        const float* hp = t ? op + (size_t)(t - 1) * BH : nullptr;
        int pin = (t - 1) & 1, pout = t & 1;
        gru_step_mma<<<128, 256>>>(hp,
            hhi + (size_t)pin * BH, hlo + (size_t)pin * BH,
            op + (size_t)t * BH,
            hhi + (size_t)pout * BH, hlo + (size_t)pout * BH,
            gates_p, whi_p, wlo_p, p_bhh, t);
    }
    // hypothesis scan: step index s = 128 + t keeps hi/lo parity consistent
    for (int t = 0; t < TDIM; t++) {
        const float* hp = (t == 0) ? op + (size_t)(TDIM - 1) * BH
                                   : hbuf + (size_t)((t - 1) & 1) * BH;
        int pin = (t + 1) & 1, pout = t & 1;   // s-1 = 127+t -> (t+1)&1 ; s = 128+t -> t&1
        gru_step_mma<<<128, 256>>>(hp,
            hhi + (size_t)pin * BH, hlo + (size_t)pin * BH,
            hbuf + (size_t)pout * BH,
            hhi + (size_t)pout * BH, hlo + (size_t)pout * BH,
            gates_h, whi_h, wlo_h, h_bhh, t);
    }
    const float* hlast = hbuf + (size_t)((TDIM - 1) & 1) * BH;

    // attention
    gemm_tf32<false><<<dim3(HDIM / 128, MB / 128), 256>>>(
        op, WyT, nullptr, WyM, MB, HDIM, HDIM);
    gemm_tiled<false, false><<<dim3(HDIM / 128, 1), 256>>>(
        hlast, W_h, nullptr, Whs, BDIM, HDIM, HDIM);
    attn_kernel<<<128, 256>>>(WyM, Whs, W_alpha, op, rs);

    // h_star and classifier
    gemm_tiled<false, false><<<dim3(HDIM / 128, 1), 256>>>(
        rs, W_p, nullptr, G1, BDIM, HDIM, HDIM);
    gemm_tiled<false, false><<<dim3(HDIM / 128, 1), 256>>>(
        hlast, W_x, nullptr, G2, BDIM, HDIM, HDIM);
    combine_tanh<<<(BH + 255) / 256, 256>>>(G1, G2, hstar, BH);
    final_kernel<<<128, 128>>>(hstar, out_w, out_b, (float*)d_out);
}

// round 3
// speedup vs baseline: 2.2230x; 1.4026x over previous
#include <cuda_runtime.h>
#include <cuda_bf16.h>
#include <math.h>
#include <stdint.h>

#define HDIM 1024
#define BDIM 128
#define TDIM 128
#define G3   (3 * HDIM)
#define BH   (BDIM * HDIM)

// ----------------------------- scratch (device globals; no allocation) ------
__device__ float g_gates_p[(size_t)BDIM * TDIM * G3];   // [B,T,3H]
__device__ float g_gates_h[(size_t)BDIM * TDIM * G3];   // [B,T,3H]
__device__ float g_op[(size_t)TDIM * BDIM * HDIM];      // premise h states, [T,B,H]
__device__ float g_hbuf[2 * BH];                        // hypothesis h ping-pong (fp32)
__device__ __nv_bfloat16 g_hhi[2 * BH];                 // h bf16 hi ping-pong
__device__ __nv_bfloat16 g_hlo[2 * BH];                 // h bf16 lo ping-pong
__device__ __nv_bfloat16 g_whi_p[(size_t)G3 * HDIM];
__device__ __nv_bfloat16 g_wlo_p[(size_t)G3 * HDIM];
__device__ __nv_bfloat16 g_whi_h[(size_t)G3 * HDIM];
__device__ __nv_bfloat16 g_wlo_h[(size_t)G3 * HDIM];
__device__ float g_WyT[HDIM * HDIM];
__device__ float g_WyM[(size_t)TDIM * BDIM * HDIM];
__device__ float g_Wh[BH];
__device__ float g_r[BH];
__device__ float g_G1[BH];
__device__ float g_G2[BH];
__device__ float g_hstar[BH];

// grid barrier state (monotonic across all launches; only mod/relative values used)
__device__ unsigned g_arrive  = 0;
__device__ unsigned g_release = 0;

__device__ __forceinline__ float sigmoidf_(float x) { return 1.0f / (1.0f + expf(-x)); }

__device__ __forceinline__ uint32_t f2tf32(float x) {
    uint32_t r;
    asm("cvt.rna.tf32.f32 %0, %1;" : "=r"(r) : "f"(x));
    return r;
}

__device__ __forceinline__ void mma_tf32(float* d, const uint32_t* a, const uint32_t* b) {
    asm("mma.sync.aligned.m16n8k8.row.col.f32.tf32.tf32.f32 "
        "{%0,%1,%2,%3},{%4,%5,%6,%7},{%8,%9},{%0,%1,%2,%3};"
        : "+f"(d[0]), "+f"(d[1]), "+f"(d[2]), "+f"(d[3])
        : "r"(a[0]), "r"(a[1]), "r"(a[2]), "r"(a[3]), "r"(b[0]), "r"(b[1]));
}

__device__ __forceinline__ void mma_bf16(float* d, const uint32_t* a, const uint32_t* b) {
    asm("mma.sync.aligned.m16n8k16.row.col.f32.bf16.bf16.f32 "
        "{%0,%1,%2,%3},{%4,%5,%6,%7},{%8,%9},{%0,%1,%2,%3};"
        : "+f"(d[0]), "+f"(d[1]), "+f"(d[2]), "+f"(d[3])
        : "r"(a[0]), "r"(a[1]), "r"(a[2]), "r"(a[3]), "r"(b[0]), "r"(b[1]));
}

__device__ __forceinline__ void cp16(void* smem_dst, const void* gsrc) {
    uint32_t d = (uint32_t)__cvta_generic_to_shared(smem_dst);
    asm volatile("cp.async.ca.shared.global [%0], [%1], 16;" :: "r"(d), "l"(gsrc));
}
#define CP_COMMIT() asm volatile("cp.async.commit_group;")
#define CP_WAIT(n)  asm volatile("cp.async.wait_group %0;" :: "n"(n))

// ----------------------------- weight split fp32 -> bf16 hi/lo ---------------
__global__ void split_w(const float* __restrict__ W, __nv_bfloat16* __restrict__ hi,
                        __nv_bfloat16* __restrict__ lo, int n)
{
    int i = blockIdx.x * blockDim.x + threadIdx.x;
    if (i < n) {
        float v = W[i];
        __nv_bfloat16 h = __float2bfloat16(v);
        hi[i] = h;
        lo[i] = __float2bfloat16(v - __bfloat162float(h));
    }
}

__global__ void transpose1024(const float* __restrict__ in, float* __restrict__ out)
{
    __shared__ float t[32][33];
    int x = blockIdx.x * 32 + threadIdx.x;
    int y0 = blockIdx.y * 32;
    for (int r = threadIdx.y; r < 32; r += 8)
        t[r][threadIdx.x] = in[(size_t)(y0 + r) * HDIM + x];
    __syncthreads();
    int xo = blockIdx.y * 32 + threadIdx.x;
    for (int r = threadIdx.y; r < 32; r += 8)
        out[(size_t)(blockIdx.x * 32 + r) * HDIM + xo] = t[threadIdx.x][r];
}

// ----------------------------- tf32 mma GEMM (unchanged from R2) -------------
template <bool BIAS>
__global__ void __launch_bounds__(256) gemm_tf32(
    const float* __restrict__ A, const float* __restrict__ Bw,
    const float* __restrict__ bias, float* __restrict__ C,
    int M, int N, int K)
{
    __shared__ uint32_t As[32][132];
    __shared__ uint32_t Bs[32][132];

    const int tid = threadIdx.x;
    const int lane = tid & 31, wid = tid >> 5;
    const int g = lane >> 2, tg = lane & 3;
    const int wm = (wid & 3) * 32;
    const int wn = (wid >> 2) * 64;
    const int m0 = blockIdx.y * 128, n0 = blockIdx.x * 128;

    float acc[2][8][4];
#pragma unroll
    for (int a = 0; a < 2; a++)
#pragma unroll
        for (int b = 0; b < 8; b++)
#pragma unroll
            for (int c = 0; c < 4; c++) acc[a][b][c] = 0.f;

    for (int k0 = 0; k0 < K; k0 += 32) {
#pragma unroll
        for (int r = 0; r < 4; r++) {
            int idx = tid + r * 256;
            int row = idx >> 3, kq = (idx & 7) * 4;
            float4 av = *(const float4*)&A[(size_t)(m0 + row) * K + k0 + kq];
            As[kq + 0][row] = f2tf32(av.x);
            As[kq + 1][row] = f2tf32(av.y);
            As[kq + 2][row] = f2tf32(av.z);
            As[kq + 3][row] = f2tf32(av.w);
            float4 bv = *(const float4*)&Bw[(size_t)(n0 + row) * K + k0 + kq];
            Bs[kq + 0][row] = f2tf32(bv.x);
            Bs[kq + 1][row] = f2tf32(bv.y);
            Bs[kq + 2][row] = f2tf32(bv.z);
            Bs[kq + 3][row] = f2tf32(bv.w);
        }
        __syncthreads();
#pragma unroll
        for (int kk = 0; kk < 32; kk += 8) {
            uint32_t af[2][4], bf[8][2];
#pragma unroll
            for (int mt = 0; mt < 2; mt++) {
                af[mt][0] = As[kk + tg][wm + mt * 16 + g];
                af[mt][1] = As[kk + tg][wm + mt * 16 + g + 8];
                af[mt][2] = As[kk + tg + 4][wm + mt * 16 + g];
                af[mt][3] = As[kk + tg + 4][wm + mt * 16 + g + 8];
            }
#pragma unroll
            for (int nt = 0; nt < 8; nt++) {
                bf[nt][0] = Bs[kk + tg][wn + nt * 8 + g];
                bf[nt][1] = Bs[kk + tg + 4][wn + nt * 8 + g];
            }
#pragma unroll
            for (int mt = 0; mt < 2; mt++)
#pragma unroll
                for (int nt = 0; nt < 8; nt++)
                    mma_tf32(acc[mt][nt], af[mt], bf[nt]);
        }
        __syncthreads();
    }

#pragma unroll
    for (int mt = 0; mt < 2; mt++) {
#pragma unroll
        for (int nt = 0; nt < 8; nt++) {
            int row = m0 + wm + mt * 16 + g;
            int col = n0 + wn + nt * 8 + 2 * tg;
            float b0 = BIAS ? bias[col] : 0.f;
            float b1 = BIAS ? bias[col + 1] : 0.f;
            C[(size_t)row * N + col]       = acc[mt][nt][0] + b0;
            C[(size_t)row * N + col + 1]   = acc[mt][nt][1] + b1;
            C[(size_t)(row + 8) * N + col]     = acc[mt][nt][2] + b0;
            C[(size_t)(row + 8) * N + col + 1] = acc[mt][nt][3] + b1;
        }
    }
}

// ----------------------------- persistent GRU scan ---------------------------
// grid = 128 blocks (block owns 8 h-cols / 24 gate rows), 256 threads.
// Weights (hi+lo bf16) resident in smem; reloaded once at s==128.
// Steps synced with a gpu-scope software grid barrier (all blocks resident:
// 128 blocks, 1/SM by smem, 148 SMs).
// smem layout (u32): Wh[24*516] Wl[24*516] | A tiles: 4 x [128*36]
#define WSTRIDE 516
#define ASTRIDE 36
#define ATILE   (128 * ASTRIDE)
#define SMEM_U32 (2 * 24 * WSTRIDE + 4 * ATILE)

__global__ void __launch_bounds__(256) gru_scan_persistent(
    const float* __restrict__ gates_p, const float* __restrict__ gates_h,
    const __nv_bfloat16* __restrict__ whi_p, const __nv_bfloat16* __restrict__ wlo_p,
    const __nv_bfloat16* __restrict__ whi_h, const __nv_bfloat16* __restrict__ wlo_h,
    const float* __restrict__ pbhh, const float* __restrict__ hbhh,
    float* __restrict__ op, float* __restrict__ hbuf,
    __nv_bfloat16* __restrict__ hhi, __nv_bfloat16* __restrict__ hlo)
{
    extern __shared__ uint32_t sm[];
    uint32_t* Wh_s = sm;
    uint32_t* Wl_s = sm + 24 * WSTRIDE;
    uint32_t* Abuf = sm + 2 * 24 * WSTRIDE;

    const int tid = threadIdx.x, lane = tid & 31, wid = tid >> 5;
    const int g = lane >> 2, tg = lane & 3;
    const int hc = blockIdx.x * 8;

    // baseline release (all blocks read before any release can happen)
    const unsigned rel0 = *(volatile unsigned*)&g_release;

    // load premise weights into smem
    {
        const uint32_t* hi = (const uint32_t*)whi_p;
        const uint32_t* lo = (const uint32_t*)wlo_p;
        for (int idx = tid; idx < 24 * 512; idx += 256) {
            int row = idx >> 9, kk = idx & 511;
            int gr  = (row >> 3) * HDIM + hc + (row & 7);
            Wh_s[row * WSTRIDE + kk] = hi[(size_t)gr * 512 + kk];
            Wl_s[row * WSTRIDE + kk] = lo[(size_t)gr * 512 + kk];
        }
    }
    __syncthreads();

    for (int s = 0; s < 256; s++) {
        const bool prem = s < 128;
        const int t = s & 127;

        if (s == 128) {   // switch to hypothesis weights
            const uint32_t* hi = (const uint32_t*)whi_h;
            const uint32_t* lo = (const uint32_t*)wlo_h;
            for (int idx = tid; idx < 24 * 512; idx += 256) {
                int row = idx >> 9, kk = idx & 511;
                int gr  = (row >> 3) * HDIM + hc + (row & 7);
                Wh_s[row * WSTRIDE + kk] = hi[(size_t)gr * 512 + kk];
                Wl_s[row * WSTRIDE + kk] = lo[(size_t)gr * 512 + kk];
            }
            __syncthreads();
        }

        const float* gx   = prem ? gates_p : gates_h;
        const float* bias = prem ? pbhh : hbhh;
        const float* hpf;
        float* hof;
        if (prem) {
            hpf = s ? op + (size_t)(s - 1) * BH : nullptr;
            hof = op + (size_t)s * BH;
        } else {
            hpf = (s == 128) ? op + (size_t)127 * BH : hbuf + (size_t)((s - 1) & 1) * BH;
            hof = hbuf + (size_t)(s & 1) * BH;
        }

        float acc[3][4];
#pragma unroll
        for (int a = 0; a < 3; a++)
#pragma unroll
            for (int c = 0; c < 4; c++) acc[a][c] = 0.f;

        if (s > 0) {
            const uint32_t* ahip = (const uint32_t*)(hhi + (size_t)((s - 1) & 1) * BH);
            const uint32_t* alop = (const uint32_t*)(hlo + (size_t)((s - 1) & 1) * BH);

            // prologue: chunk 0 -> buf 0
            {
                uint32_t* Ah = Abuf;
                uint32_t* Al = Abuf + ATILE;
#pragma unroll
                for (int v = 0; v < 4; v++) {
                    int lin = tid + v * 256;
                    int row = lin >> 3, c4 = (lin & 7) * 4;
                    cp16(&Ah[row * ASTRIDE + c4], ahip + (size_t)row * 512 + c4);
                    cp16(&Al[row * ASTRIDE + c4], alop + (size_t)row * 512 + c4);
                }
                CP_COMMIT();
            }

            for (int c = 0; c < 16; c++) {
                if (c + 1 < 16) {
                    uint32_t* Ah = Abuf + ((c + 1) & 1) * 2 * ATILE;
                    uint32_t* Al = Ah + ATILE;
                    const uint32_t* hsrc = ahip + (c + 1) * 32;
                    const uint32_t* lsrc = alop + (c + 1) * 32;
#pragma unroll
                    for (int v = 0; v < 4; v++) {
                        int lin = tid + v * 256;
                        int row = lin >> 3, c4 = (lin & 7) * 4;
                        cp16(&Ah[row * ASTRIDE + c4], hsrc + (size_t)row * 512 + c4);
                        cp16(&Al[row * ASTRIDE + c4], lsrc + (size_t)row * 512 + c4);
                    }
                    CP_COMMIT();
                    CP_WAIT(1);
                } else {
                    CP_WAIT(0);
                }
                __syncthreads();

                const uint32_t* Ah = Abuf + (c & 1) * 2 * ATILE;
                const uint32_t* Al = Ah + ATILE;
#pragma unroll
                for (int s4 = 0; s4 < 4; s4++) {
                    const int kc = s4 * 8;
                    uint32_t AH[4], AL[4];
                    AH[0] = Ah[(wid * 16 + g) * ASTRIDE + kc + tg];
                    AH[1] = Ah[(wid * 16 + g + 8) * ASTRIDE + kc + tg];
                    AH[2] = Ah[(wid * 16 + g) * ASTRIDE + kc + tg + 4];
                    AH[3] = Ah[(wid * 16 + g + 8) * ASTRIDE + kc + tg + 4];
                    AL[0] = Al[(wid * 16 + g) * ASTRIDE + kc + tg];
                    AL[1] = Al[(wid * 16 + g + 8) * ASTRIDE + kc + tg];
                    AL[2] = Al[(wid * 16 + g) * ASTRIDE + kc + tg + 4];
                    AL[3] = Al[(wid * 16 + g + 8) * ASTRIDE + kc + tg + 4];
#pragma unroll
                    for (int gt = 0; gt < 3; gt++) {
                        const int wb = (gt * 8 + g) * WSTRIDE + c * 32 + kc + tg;
                        uint32_t BH_[2], BL_[2];
                        BH_[0] = Wh_s[wb];
                        BH_[1] = Wh_s[wb + 4];
                        BL_[0] = Wl_s[wb];
                        BL_[1] = Wl_s[wb + 4];
                        mma_bf16(acc[gt], AH, BH_);
                        mma_bf16(acc[gt], AH, BL_);
                        mma_bf16(acc[gt], AL, BH_);
                    }
                }
                __syncthreads();
            }
        }

        // epilogue: thread owns batches {16w+g, 16w+g+8} x cols {hc+2tg, hc+2tg+1}
        const int brow = wid * 16 + g;
#pragma unroll
        for (int i = 0; i < 2; i++) {
            int b = brow + i * 8;
#pragma unroll
            for (int jj = 0; jj < 2; jj++) {
                int col = hc + 2 * tg + jj;
                int ai = i * 2 + jj;
                size_t gbase = ((size_t)b * TDIM + t) * G3;
                float r = sigmoidf_(gx[gbase + col] + acc[0][ai] + bias[col]);
                float z = sigmoidf_(gx[gbase + HDIM + col] + acc[1][ai] + bias[HDIM + col]);
                float n = tanhf(gx[gbase + 2 * HDIM + col] + r * (acc[2][ai] + bias[2 * HDIM + col]));
                float hp = hpf ? hpf[(size_t)b * HDIM + col] : 0.f;
                float h = (1.f - z) * n + z * hp;
                size_t oi = (size_t)b * HDIM + col;
                hof[oi] = h;
                __nv_bfloat16 hb = __float2bfloat16(h);
                size_t pi = (size_t)(s & 1) * BH + oi;
                hhi[pi] = hb;
                hlo[pi] = __float2bfloat16(h - __bfloat162float(hb));
            }
        }

        // grid barrier
        __threadfence();
        __syncthreads();
        if (tid == 0) {
            unsigned r = atomicAdd(&g_arrive, 1u);
            if ((r & 127u) == 127u) atomicAdd(&g_release, 1u);
            while ((unsigned)(*(volatile unsigned*)&g_release - rel0) < (unsigned)(s + 1))
                __nanosleep(32);
            __threadfence();
        }
        __syncthreads();
    }
}

// ----------------------------- fp32 GEMM for small matmuls -------------------
template <bool TRANSB, bool BIAS>
__global__ void gemm_tiled(const float* __restrict__ A, const float* __restrict__ Bm,
                           const float* __restrict__ bias, float* __restrict__ C,
                           int M, int N, int K)
{
    __shared__ float As[8][132];
    __shared__ float Bs[8][132];

    const int tid = threadIdx.x;
    const int tx = tid & 15, ty = tid >> 4;
    const int m0 = blockIdx.y * 128, n0 = blockIdx.x * 128;

    float acc[8][8];
#pragma unroll
    for (int i = 0; i < 8; i++)
#pragma unroll
        for (int j = 0; j < 8; j++) acc[i][j] = 0.f;

    const int a_row = tid >> 1;
    const int a_k4  = (tid & 1) * 4;
    const int b_kr  = tid >> 5;
    const int b_n4  = (tid & 31) * 4;

    for (int k0 = 0; k0 < K; k0 += 8) {
        float4 av = *(const float4*)&A[(size_t)(m0 + a_row) * K + k0 + a_k4];
        As[a_k4 + 0][a_row] = av.x;
        As[a_k4 + 1][a_row] = av.y;
        As[a_k4 + 2][a_row] = av.z;
        As[a_k4 + 3][a_row] = av.w;
        if (TRANSB) {
            float4 bv = *(const float4*)&Bm[(size_t)(n0 + a_row) * K + k0 + a_k4];
            Bs[a_k4 + 0][a_row] = bv.x;
            Bs[a_k4 + 1][a_row] = bv.y;
            Bs[a_k4 + 2][a_row] = bv.z;
            Bs[a_k4 + 3][a_row] = bv.w;
        } else {
            float4 bv = *(const float4*)&Bm[(size_t)(k0 + b_kr) * N + n0 + b_n4];
            Bs[b_kr][b_n4 + 0] = bv.x;
            Bs[b_kr][b_n4 + 1] = bv.y;
            Bs[b_kr][b_n4 + 2] = bv.z;
            Bs[b_kr][b_n4 + 3] = bv.w;
        }
        __syncthreads();
#pragma unroll
        for (int kk = 0; kk < 8; kk++) {
            float a[8], b[8];
#pragma unroll
            for (int i = 0; i < 8; i++) a[i] = As[kk][ty + 16 * i];
#pragma unroll
            for (int j = 0; j < 8; j++) b[j] = Bs[kk][tx + 16 * j];
#pragma unroll
            for (int i = 0; i < 8; i++)
#pragma unroll
                for (int j = 0; j < 8; j++) acc[i][j] += a[i] * b[j];
        }
        __syncthreads();
    }

#pragma unroll
    for (int i = 0; i < 8; i++) {
        int m = m0 + ty + 16 * i;
#pragma unroll
        for (int j = 0; j < 8; j++) {
            int n = n0 + tx + 16 * j;
            float v = acc[i][j];
            if (BIAS) v += bias[n];
            C[(size_t)m * N + n] = v;
        }
    }
}

// ----------------------------- attention -------------------------------------
__global__ void attn_kernel(const float* __restrict__ WyM, const float* __restrict__ Wh,
                            const float* __restrict__ Walpha, const float* __restrict__ op,
                            float* __restrict__ rout)
{
    __shared__ float sc[128];
    __shared__ float red[256];
    const int b = blockIdx.x;
    const int tid = threadIdx.x;
    const int lane = tid & 31;
    const int warp = tid >> 5;

    for (int t = warp; t < TDIM; t += 8) {
        const float* wy = WyM + ((size_t)t * BDIM + b) * HDIM;
        const float* wh = Wh + (size_t)b * HDIM;
        float s = 0.f;
        for (int d = lane; d < HDIM; d += 32)
            s += tanhf(wy[d] + wh[d]) * Walpha[d];
#pragma unroll
        for (int o = 16; o > 0; o >>= 1) s += __shfl_xor_sync(0xffffffffu, s, o);
        if (lane == 0) sc[t] = s;
    }
    __syncthreads();

    float v = (tid < 128) ? sc[tid] : -INFINITY;
    red[tid] = v;
    __syncthreads();
    for (int s = 128; s > 0; s >>= 1) {
        if (tid < s) red[tid] = fmaxf(red[tid], red[tid + s]);
        __syncthreads();
    }
    float mx = red[0];
    __syncthreads();
    float e = (tid < 128) ? expf(sc[tid] - mx) : 0.f;
    red[tid] = e;
    __syncthreads();
    for (int s = 128; s > 0; s >>= 1) {
        if (tid < s) red[tid] += red[tid + s];
        __syncthreads();
    }
    float sum = red[0];
    __syncthreads();
    if (tid < 128) sc[tid] = e / sum;
    __syncthreads();

    for (int h = tid; h < HDIM; h += 256) {
        float acc = 0.f;
        for (int t = 0; t < TDIM; t++)
            acc += sc[t] * op[((size_t)t * BDIM + b) * HDIM + h];
        rout[(size_t)b * HDIM + h] = acc;
    }
}

__global__ void combine_tanh(const float* __restrict__ a, const float* __restrict__ b,
                             float* __restrict__ c, int n)
{
    int i = blockIdx.x * blockDim.x + threadIdx.x;
    if (i < n) c[i] = tanhf(a[i] + b[i]);
}

__global__ void final_kernel(const float* __restrict__ hstar, const float* __restrict__ outw,
                             const float* __restrict__ outb, float* __restrict__ out)
{
    __shared__ float red[128];
    __shared__ float lg[3];
    const int b = blockIdx.x;
    const int tid = threadIdx.x;

    for (int c = 0; c < 3; c++) {
        float p = 0.f;
        for (int h = tid; h < HDIM; h += 128)
            p += hstar[(size_t)b * HDIM + h] * outw[(size_t)c * HDIM + h];
        red[tid] = p;
        __syncthreads();
        for (int s = 64; s > 0; s >>= 1) {
            if (tid < s) red[tid] += red[tid + s];
            __syncthreads();
        }
        if (tid == 0) lg[c] = tanhf(red[0] + outb[c]);
        __syncthreads();
    }
    if (tid == 0) {
        float m = fmaxf(lg[0], fmaxf(lg[1], lg[2]));
        float s = expf(lg[0] - m) + expf(lg[1] - m) + expf(lg[2] - m);
        float lse = logf(s);
        for (int c = 0; c < 3; c++) out[b * 3 + c] = lg[c] - m - lse;
    }
}

// ----------------------------- launch ----------------------------------------
extern "C" void kernel_launch(void* const* d_in, const int* in_sizes, int n_in,
                              void* d_out, int out_size)
{
    const float* premise    = (const float*)d_in[0];
    const float* hypothesis = (const float*)d_in[1];
    const float* p_Wih = (const float*)d_in[2];
    const float* p_Whh = (const float*)d_in[3];
    const float* p_bih = (const float*)d_in[4];
    const float* p_bhh = (const float*)d_in[5];
    const float* h_Wih = (const float*)d_in[6];
    const float* h_Whh = (const float*)d_in[7];
    const float* h_bih = (const float*)d_in[8];
    const float* h_bhh = (const float*)d_in[9];
    const float* W_y     = (const float*)d_in[10];
    const float* W_h     = (const float*)d_in[11];
    const float* W_alpha = (const float*)d_in[12];
    const float* W_x     = (const float*)d_in[13];
    const float* W_p     = (const float*)d_in[14];
    const float* out_w   = (const float*)d_in[15];
    const float* out_b   = (const float*)d_in[16];

    float *gates_p, *gates_h, *op, *hbuf, *WyT, *WyM, *Whs, *rs, *G1, *G2, *hstar;
    __nv_bfloat16 *hhi, *hlo, *whi_p, *wlo_p, *whi_h, *wlo_h;
    cudaGetSymbolAddress((void**)&gates_p, g_gates_p);
    cudaGetSymbolAddress((void**)&gates_h, g_gates_h);
    cudaGetSymbolAddress((void**)&op,      g_op);
    cudaGetSymbolAddress((void**)&hbuf,    g_hbuf);
    cudaGetSymbolAddress((void**)&hhi,     g_hhi);
    cudaGetSymbolAddress((void**)&hlo,     g_hlo);
    cudaGetSymbolAddress((void**)&whi_p,   g_whi_p);
    cudaGetSymbolAddress((void**)&wlo_p,   g_wlo_p);
    cudaGetSymbolAddress((void**)&whi_h,   g_whi_h);
    cudaGetSymbolAddress((void**)&wlo_h,   g_wlo_h);
    cudaGetSymbolAddress((void**)&WyT,     g_WyT);
    cudaGetSymbolAddress((void**)&WyM,     g_WyM);
    cudaGetSymbolAddress((void**)&Whs,     g_Wh);
    cudaGetSymbolAddress((void**)&rs,      g_r);
    cudaGetSymbolAddress((void**)&G1,      g_G1);
    cudaGetSymbolAddress((void**)&G2,      g_G2);
    cudaGetSymbolAddress((void**)&hstar,   g_hstar);

    const int MB = TDIM * BDIM;

    // prep
    split_w<<<(G3 * HDIM + 255) / 256, 256>>>(p_Whh, whi_p, wlo_p, G3 * HDIM);
    split_w<<<(G3 * HDIM + 255) / 256, 256>>>(h_Whh, whi_h, wlo_h, G3 * HDIM);
    transpose1024<<<dim3(32, 32), dim3(32, 8)>>>(W_y, WyT);

    // input-gate GEMMs
    gemm_tf32<true><<<dim3(G3 / 128, MB / 128), 256>>>(
        premise, p_Wih, p_bih, gates_p, MB, G3, HDIM);
    gemm_tf32<true><<<dim3(G3 / 128, MB / 128), 256>>>(
        hypothesis, h_Wih, h_bih, gates_h, MB, G3, HDIM);

    // persistent scan: both GRUs, 256 steps, one launch
    static bool attr_set = false;
    if (!attr_set) {
        cudaFuncSetAttribute(gru_scan_persistent,
                             cudaFuncAttributeMaxDynamicSharedMemorySize,
                             SMEM_U32 * 4);
        attr_set = true;
    }
    gru_scan_persistent<<<128, 256, SMEM_U32 * 4>>>(
        gates_p, gates_h, whi_p, wlo_p, whi_h, wlo_h,
        p_bhh, h_bhh, op, hbuf, hhi, hlo);

    const float* hlast = hbuf + (size_t)((TDIM - 1) & 1) * BH;

    // attention
    gemm_tf32<false><<<dim3(HDIM / 128, MB / 128), 256>>>(
        op, WyT, nullptr, WyM, MB, HDIM, HDIM);
    gemm_tiled<false, false><<<dim3(HDIM / 128, 1), 256>>>(
        hlast, W_h, nullptr, Whs, BDIM, HDIM, HDIM);
    attn_kernel<<<128, 256>>>(WyM, Whs, W_alpha, op, rs);

    // h_star and classifier
    gemm_tiled<false, false><<<dim3(HDIM / 128, 1), 256>>>(
        rs, W_p, nullptr, G1, BDIM, HDIM, HDIM);
    gemm_tiled<false, false><<<dim3(HDIM / 128, 1), 256>>>(
        hlast, W_x, nullptr, G2, BDIM, HDIM, HDIM);
    combine_tanh<<<(BH + 255) / 256, 256>>>(G1, G2, hstar, BH);
    final_kernel<<<128, 128>>>(hstar, out_w, out_b, (float*)d_out);
}